// round 15
// baseline (speedup 1.0000x reference)
#include <cuda_runtime.h>
#include <math.h>
#include <cstdint>

// ---------------------------------------------------------------------------
// Retention, fully parallel chunked formulation (all FFMA2 / f32x2):
//   xT = x^T                                                 (transpose)
//   proj: qkv = x @ Wqkv + b  (cp.async double-buffered)     (GEMM)
//   intra: out = (tril(alpha^{r-p}) * qk^T/16) @ V   ─┐ merged single launch
//   G_t[m,n] = sum_r alpha^(127-r) k[r,m] v[r,n]     ─┘
//   S_t = alpha^128 * S_{t-1} + G_{t-1}                      (elementwise scan)
//   inter: out += alpha^(r+1)/16 * q @ S_t                   (GEMM)
// ---------------------------------------------------------------------------

#define BB    8
#define LL    4096
#define DD    256
#define CC    128
#define TT    (LL / CC)
#define NQKV  768
#define MTOT  (BB * LL)
#define ALPHAF 0.99f

typedef unsigned long long u64t;

__device__ __forceinline__ u64t pk2(float a, float b) {
    u64t r; asm("mov.b64 %0, {%1,%2};" : "=l"(r) : "f"(a), "f"(b)); return r;
}
__device__ __forceinline__ void up2(u64t v, float& a, float& b) {
    asm("mov.b64 {%0,%1}, %2;" : "=f"(a), "=f"(b) : "l"(v));
}
__device__ __forceinline__ u64t ffma2(u64t a, u64t b, u64t c) {
    u64t d; asm("fma.rn.f32x2 %0, %1, %2, %3;" : "=l"(d) : "l"(a), "l"(b), "l"(c)); return d;
}
__device__ __forceinline__ uint32_t smem_u32(const void* p) {
    uint32_t a;
    asm("{ .reg .u64 t; cvta.to.shared.u64 t, %1; cvt.u32.u64 %0, t; }"
        : "=r"(a) : "l"(p));
    return a;
}
__device__ __forceinline__ void cpa16(uint32_t dst, const void* src) {
    asm volatile("cp.async.ca.shared.global [%0], [%1], 16;" :: "r"(dst), "l"(src));
}
#define CPA_COMMIT() asm volatile("cp.async.commit_group;" ::: "memory")
#define CPA_WAIT(n)  asm volatile("cp.async.wait_group %0;" :: "n"(n) : "memory")

// ---- scratch (device globals; no runtime allocation) -----------------------
__device__ float g_q[MTOT * DD];
__device__ float g_k[MTOT * DD];
__device__ float g_v[MTOT * DD];
__device__ float g_G[BB * TT * DD * DD];   // G chunks, then S in-place
__device__ float g_xT[DD * MTOT];          // x transposed [k][m]

// 8x8 f32x2 microkernel step (proven): A broadcast via pk2, B as pairs.
#define MK_STEP(Abase, Bbase)                                                  \
    do {                                                                       \
        const float4 a0 = *(const float4*)(Abase);                             \
        const float4 a1 = *(const float4*)((Abase) + 4);                       \
        const u64t* wp = (const u64t*)(Bbase);                                 \
        const u64t w0 = wp[0], w1 = wp[1], w2 = wp[2], w3 = wp[3];             \
        float av[8] = {a0.x, a0.y, a0.z, a0.w, a1.x, a1.y, a1.z, a1.w};        \
        _Pragma("unroll")                                                      \
        for (int i = 0; i < 8; ++i) {                                          \
            u64t aa = pk2(av[i], av[i]);                                       \
            acc[i][0] = ffma2(aa, w0, acc[i][0]);                              \
            acc[i][1] = ffma2(aa, w1, acc[i][1]);                              \
            acc[i][2] = ffma2(aa, w2, acc[i][2]);                              \
            acc[i][3] = ffma2(aa, w3, acc[i][3]);                              \
        }                                                                      \
    } while (0)

// ===========================================================================
// Kernel 0: transpose x[32768][256] -> xT[256][32768]
// ===========================================================================
__global__ void k_xT(const float* __restrict__ x) {
    __shared__ float t[32][33];
    const int m0 = blockIdx.x * 32;
    const int k0 = blockIdx.y * 32;
    const int i = threadIdx.x >> 5, j = threadIdx.x & 31;
    #pragma unroll
    for (int l = 0; l < 4; ++l) {
        int row = i + l * 8;
        t[row][j] = x[(size_t)(m0 + row) * DD + k0 + j];
    }
    __syncthreads();
    #pragma unroll
    for (int l = 0; l < 4; ++l) {
        int row = i + l * 8;
        g_xT[(size_t)(k0 + row) * MTOT + m0 + j] = t[j][row];
    }
}

// ===========================================================================
// Kernel 1: QKV projection with cp.async double-buffered staging.
// Dyn smem: 2 buffers x (Xs[32][132] + Ws[32][132]) = 67584 B; 3 CTAs/SM.
// ===========================================================================
#define PROJ_SMEM (2 * 2 * 32 * 132 * 4)

__global__ void __launch_bounds__(256, 3)
k_proj(const float* __restrict__ W, const float* __restrict__ bias) {
    extern __shared__ __align__(16) float smf[];
    const uint32_t smem_u = smem_u32(smf);

    const int tid = threadIdx.x;
    const int ty = tid >> 4, tx = tid & 15;
    const int m0 = blockIdx.x * 128;
    const int n0 = blockIdx.y * 128;

    auto issue = [&](int kt, int buf) {
        const uint32_t xb = smem_u + buf * (8448 * 4);
        const uint32_t wb = xb + 4224 * 4;
        #pragma unroll
        for (int it = 0; it < 4; ++it) {
            int c = tid + it * 256;         // 0..1023
            int kk = c >> 5, c4 = c & 31;
            cpa16(xb + (kk * 132 + c4 * 4) * 4,
                  g_xT + (size_t)(kt * 32 + kk) * MTOT + m0 + c4 * 4);
            cpa16(wb + (kk * 132 + c4 * 4) * 4,
                  W + (size_t)(kt * 32 + kk) * NQKV + n0 + c4 * 4);
        }
    };

    issue(0, 0);
    CPA_COMMIT();

    u64t acc[8][4] = {};

    for (int kt = 0; kt < 8; ++kt) {
        const int buf = kt & 1;
        if (kt < 7) { issue(kt + 1, buf ^ 1); CPA_COMMIT(); CPA_WAIT(1); }
        else        { CPA_WAIT(0); }
        __syncthreads();

        const float* Xb = smf + buf * 8448;
        const float* Wb = Xb + 4224;
        #pragma unroll
        for (int kk = 0; kk < 32; ++kk)
            MK_STEP(Xb + kk * 132 + ty * 8, Wb + kk * 132 + tx * 8);

        __syncthreads();   // safe to overwrite this buffer next-next iter
    }

    const int cg0 = n0 + tx * 8;
    const int which = cg0 >> 8;
    float* dst = (which == 0) ? g_q : (which == 1 ? g_k : g_v);
    const int off = cg0 & 255;
    float bv[8];
    #pragma unroll
    for (int u = 0; u < 8; ++u) bv[u] = bias[cg0 + u];

    #pragma unroll
    for (int i = 0; i < 8; ++i) {
        size_t mg = (size_t)(m0 + ty * 8 + i);
        float o[8];
        up2(acc[i][0], o[0], o[1]); up2(acc[i][1], o[2], o[3]);
        up2(acc[i][2], o[4], o[5]); up2(acc[i][3], o[6], o[7]);
        *(float4*)(dst + mg * DD + off) =
            make_float4(o[0] + bv[0], o[1] + bv[1], o[2] + bv[2], o[3] + bv[3]);
        *(float4*)(dst + mg * DD + off + 4) =
            make_float4(o[4] + bv[4], o[5] + bv[5], o[6] + bv[6], o[7] + bv[7]);
    }
}

// ===========================================================================
// Kernel 2 (merged): blockIdx < 256 -> fused intra (scores + A@V);
//                    blockIdx >= 256 -> chunk summaries G.
// Dyn smem = 101376 B (scores2 layout; G uses a prefix of it). 2 CTAs/SM.
// ===========================================================================
#define SG_SMEM ((128 * 132 + 2 * 32 * 132) * 4)

__device__ void scores2_body(int bx, float* __restrict__ out, float* smf) {
    float* As = smf;                  // [128][132]
    float* Qs = As + 128 * 132;       // [32][132]
    float* Ks = Qs + 32 * 132;        // [32][132]
    float* Vt = Qs;                   // [32][132] (aliases Qs in phase 2)
    __shared__ float tabB[128];

    const int tid = threadIdx.x;
    const int ty = tid >> 4, tx = tid & 15;
    const int bi = bx >> 5;
    const int t  = bx & 31;
    const size_t rowbase = (size_t)bi * LL + (size_t)t * CC;

    if (tid < 128) tabB[tid] = powf(ALPHAF, (float)tid) * 0.0625f;

    // ---- phase 1: scores, reg-prefetched ----
    {
        float rq[16], rk[16];
        #pragma unroll
        for (int it = 0; it < 16; ++it) {
            int idx = tid + it * 256;
            int kk = idx & 31, rr = idx >> 5;
            rq[it] = g_q[(rowbase + rr) * DD + kk];
            rk[it] = g_k[(rowbase + rr) * DD + kk];
        }

        u64t acc[8][4] = {};

        for (int kt = 0; kt < 8; ++kt) {
            __syncthreads();
            #pragma unroll
            for (int it = 0; it < 16; ++it) {
                int idx = tid + it * 256;
                int kk = idx & 31, rr = idx >> 5;
                Qs[kk * 132 + rr] = rq[it];
                Ks[kk * 132 + rr] = rk[it];
            }
            __syncthreads();

            if (kt < 7) {
                #pragma unroll
                for (int it = 0; it < 16; ++it) {
                    int idx = tid + it * 256;
                    int kk = idx & 31, rr = idx >> 5;
                    rq[it] = g_q[(rowbase + rr) * DD + (kt + 1) * 32 + kk];
                    rk[it] = g_k[(rowbase + rr) * DD + (kt + 1) * 32 + kk];
                }
            }

            #pragma unroll
            for (int kk = 0; kk < 32; ++kk)
                MK_STEP(Qs + kk * 132 + ty * 8, Ks + kk * 132 + tx * 8);
        }

        // decay + mask, park A in smem
        #pragma unroll
        for (int i = 0; i < 8; ++i) {
            const int rr = ty * 8 + i;
            float o[8];
            up2(acc[i][0], o[0], o[1]); up2(acc[i][1], o[2], o[3]);
            up2(acc[i][2], o[4], o[5]); up2(acc[i][3], o[6], o[7]);
            #pragma unroll
            for (int u = 0; u < 8; ++u) {
                int pp = tx * 8 + u;
                o[u] = (pp <= rr) ? o[u] * tabB[rr - pp] : 0.0f;
            }
            *(float4*)(As + rr * 132 + tx * 8)     = make_float4(o[0], o[1], o[2], o[3]);
            *(float4*)(As + rr * 132 + tx * 8 + 4) = make_float4(o[4], o[5], o[6], o[7]);
        }
    }

    // ---- phase 2: out = A @ V; V streamed as 8 tiles of 32 rows ----
    {
        float rv[16];
        #pragma unroll
        for (int it = 0; it < 16; ++it) {
            int idx = tid + it * 256;
            rv[it] = g_v[(rowbase + (idx >> 7)) * DD + (idx & 127)];
        }

        for (int nh = 0; nh < 2; ++nh) {
            u64t acc[8][4] = {};
            for (int jt = 0; jt < 4; ++jt) {
                const int s = nh * 4 + jt;
                __syncthreads();
                #pragma unroll
                for (int it = 0; it < 16; ++it) {
                    int idx = tid + it * 256;
                    Vt[(idx >> 7) * 132 + (idx & 127)] = rv[it];
                }
                __syncthreads();

                if (s < 7) {
                    const int nh2 = (s + 1) >> 2, jt2 = (s + 1) & 3;
                    #pragma unroll
                    for (int it = 0; it < 16; ++it) {
                        int idx = tid + it * 256;
                        rv[it] = g_v[(rowbase + jt2 * 32 + (idx >> 7)) * DD
                                     + nh2 * 128 + (idx & 127)];
                    }
                }

                #pragma unroll
                for (int j4 = 0; j4 < 8; ++j4) {
                    float av[8][4];
                    #pragma unroll
                    for (int i = 0; i < 8; ++i)
                        *(float4*)av[i] =
                            *(const float4*)(As + (ty * 8 + i) * 132 + jt * 32 + j4 * 4);
                    #pragma unroll
                    for (int jj = 0; jj < 4; ++jj) {
                        const u64t* vp = (const u64t*)(Vt + (j4 * 4 + jj) * 132 + tx * 8);
                        const u64t w0 = vp[0], w1 = vp[1], w2 = vp[2], w3 = vp[3];
                        #pragma unroll
                        for (int i = 0; i < 8; ++i) {
                            u64t aa = pk2(av[i][jj], av[i][jj]);
                            acc[i][0] = ffma2(aa, w0, acc[i][0]);
                            acc[i][1] = ffma2(aa, w1, acc[i][1]);
                            acc[i][2] = ffma2(aa, w2, acc[i][2]);
                            acc[i][3] = ffma2(aa, w3, acc[i][3]);
                        }
                    }
                }
            }

            #pragma unroll
            for (int i = 0; i < 8; ++i) {
                float o[8];
                up2(acc[i][0], o[0], o[1]); up2(acc[i][1], o[2], o[3]);
                up2(acc[i][2], o[4], o[5]); up2(acc[i][3], o[6], o[7]);
                float* op = out + (rowbase + ty * 8 + i) * DD + nh * 128 + tx * 8;
                *(float4*)op       = make_float4(o[0], o[1], o[2], o[3]);
                *(float4*)(op + 4) = make_float4(o[4], o[5], o[6], o[7]);
            }
        }
    }
}

__device__ void G_body(int bx, float* smf) {
    float* Kd = smf;                  // [32][132]
    float* Vs = Kd + 32 * 132;        // [32][132]
    __shared__ float tabA[128];

    const int tid = threadIdx.x;
    const int ty = tid >> 4, tx = tid & 15;
    const int bt = bx >> 2;
    const int quad = bx & 3;
    const int mi = quad >> 1, ni = quad & 1;
    const int b = bt >> 5, t = bt & 31;
    const size_t rowbase = (size_t)b * LL + (size_t)t * CC;

    if (tid < 128) tabA[tid] = powf(ALPHAF, (float)(127 - tid));
    __syncthreads();

    float4 rk4[4], rv4[4];
    #pragma unroll
    for (int it = 0; it < 4; ++it) {
        int i4 = tid + it * 256;
        int m4 = i4 & 31, rr = i4 >> 5;
        rk4[it] = *(const float4*)(g_k + (rowbase + rr) * DD + mi * 128 + m4 * 4);
        rv4[it] = *(const float4*)(g_v + (rowbase + rr) * DD + ni * 128 + m4 * 4);
    }

    u64t acc[8][4] = {};

    for (int rt = 0; rt < 4; ++rt) {
        __syncthreads();
        #pragma unroll
        for (int it = 0; it < 4; ++it) {
            int i4 = tid + it * 256;
            int m4 = i4 & 31, rr = i4 >> 5;
            float sc = tabA[rt * 32 + rr];
            *(float4*)(Kd + rr * 132 + m4 * 4) =
                make_float4(rk4[it].x * sc, rk4[it].y * sc, rk4[it].z * sc, rk4[it].w * sc);
            *(float4*)(Vs + rr * 132 + m4 * 4) = rv4[it];
        }
        __syncthreads();

        if (rt < 3) {
            #pragma unroll
            for (int it = 0; it < 4; ++it) {
                int i4 = tid + it * 256;
                int m4 = i4 & 31, rr = i4 >> 5;
                rk4[it] = *(const float4*)(g_k + (rowbase + (rt + 1) * 32 + rr) * DD
                                           + mi * 128 + m4 * 4);
                rv4[it] = *(const float4*)(g_v + (rowbase + (rt + 1) * 32 + rr) * DD
                                           + ni * 128 + m4 * 4);
            }
        }

        #pragma unroll
        for (int kk = 0; kk < 32; ++kk)
            MK_STEP(Kd + kk * 132 + ty * 8, Vs + kk * 132 + tx * 8);
    }

    float* Gd = g_G + ((size_t)bt << 16);
    #pragma unroll
    for (int i = 0; i < 8; ++i) {
        float o[8];
        up2(acc[i][0], o[0], o[1]); up2(acc[i][1], o[2], o[3]);
        up2(acc[i][2], o[4], o[5]); up2(acc[i][3], o[6], o[7]);
        float* gp = Gd + (size_t)(mi * 128 + ty * 8 + i) * DD + ni * 128 + tx * 8;
        *(float4*)gp       = make_float4(o[0], o[1], o[2], o[3]);
        *(float4*)(gp + 4) = make_float4(o[4], o[5], o[6], o[7]);
    }
}

__global__ void __launch_bounds__(256, 2) k_sg(float* __restrict__ out) {
    extern __shared__ __align__(16) float smf[];
    if (blockIdx.x < 256) scores2_body(blockIdx.x, out, smf);   // long CTAs first
    else                  G_body(blockIdx.x - 256, smf);
}

// ===========================================================================
// Kernel 3: elementwise prefix scan, 2-deep prefetch (MLP 3).
// ===========================================================================
__global__ void k_prefix() {
    const int id = blockIdx.x * 256 + threadIdx.x;
    const int b = id >> 14;
    const int e4 = id & 16383;
    float4* p = (float4*)g_G + ((size_t)b * 32) * 16384 + e4;
    const float a128 = powf(ALPHAF, 128.0f);
    float4 s = make_float4(0.f, 0.f, 0.f, 0.f);
    float4 g0 = p[0];
    float4 g1 = p[16384];
    #pragma unroll
    for (int t = 0; t < TT; ++t) {
        float4 gn = make_float4(0.f, 0.f, 0.f, 0.f);
        if (t + 2 < TT) gn = p[(size_t)(t + 2) * 16384];
        p[(size_t)t * 16384] = s;
        s.x = fmaf(a128, s.x, g0.x); s.y = fmaf(a128, s.y, g0.y);
        s.z = fmaf(a128, s.z, g0.z); s.w = fmaf(a128, s.w, g0.w);
        g0 = g1; g1 = gn;
    }
}

// ===========================================================================
// Kernel 4: inter-chunk: out += alpha^(r+1)/16 * q @ S_t   (496 CTAs exact)
// ===========================================================================
__global__ void __launch_bounds__(256, 2) k_inter(float* __restrict__ out) {
    const int b  = blockIdx.x / 62;
    const int r  = blockIdx.x % 62;
    const int t  = (r >> 1) + 1;         // 1..31
    const int nh = r & 1;
    const int bt = b * 32 + t;

    __shared__ __align__(16) float Qs[32 * 132];
    __shared__ __align__(16) float Ss[32 * 132];

    const int tid = threadIdx.x;
    const int ty = tid >> 4, tx = tid & 15;
    const size_t rowbase = (size_t)b * LL + (size_t)t * CC;
    const float* Sbase = g_G + ((size_t)bt << 16);

    float rq[16];
    float4 rs4[4];
    #pragma unroll
    for (int it = 0; it < 16; ++it) {
        int idx = tid + it * 256;
        rq[it] = g_q[(rowbase + (idx >> 5)) * DD + (idx & 31)];
    }
    #pragma unroll
    for (int it = 0; it < 4; ++it) {
        int i4 = tid + it * 256;
        rs4[it] = *(const float4*)(Sbase + (size_t)(i4 >> 5) * DD + nh * 128 + (i4 & 31) * 4);
    }

    u64t acc[8][4] = {};

    for (int kt = 0; kt < 8; ++kt) {
        __syncthreads();
        #pragma unroll
        for (int it = 0; it < 16; ++it) {
            int idx = tid + it * 256;
            Qs[(idx & 31) * 132 + (idx >> 5)] = rq[it];
        }
        #pragma unroll
        for (int it = 0; it < 4; ++it) {
            int i4 = tid + it * 256;
            *(float4*)(Ss + (i4 >> 5) * 132 + (i4 & 31) * 4) = rs4[it];
        }
        __syncthreads();

        if (kt < 7) {
            #pragma unroll
            for (int it = 0; it < 16; ++it) {
                int idx = tid + it * 256;
                rq[it] = g_q[(rowbase + (idx >> 5)) * DD + (kt + 1) * 32 + (idx & 31)];
            }
            #pragma unroll
            for (int it = 0; it < 4; ++it) {
                int i4 = tid + it * 256;
                rs4[it] = *(const float4*)(Sbase + (size_t)((kt + 1) * 32 + (i4 >> 5)) * DD
                                           + nh * 128 + (i4 & 31) * 4);
            }
        }

        #pragma unroll
        for (int kk = 0; kk < 32; ++kk)
            MK_STEP(Qs + kk * 132 + ty * 8, Ss + kk * 132 + tx * 8);
    }

    #pragma unroll
    for (int i = 0; i < 8; ++i) {
        const int rr = ty * 8 + i;
        const float sc = powf(ALPHAF, (float)(rr + 1)) * 0.0625f;
        float o[8];
        up2(acc[i][0], o[0], o[1]); up2(acc[i][1], o[2], o[3]);
        up2(acc[i][2], o[4], o[5]); up2(acc[i][3], o[6], o[7]);
        float* op = out + (rowbase + rr) * DD + nh * 128 + tx * 8;
        float4 c0 = *(const float4*)op;
        float4 c1 = *(const float4*)(op + 4);
        *(float4*)op = make_float4(c0.x + sc * o[0], c0.y + sc * o[1],
                                   c0.z + sc * o[2], c0.w + sc * o[3]);
        *(float4*)(op + 4) = make_float4(c1.x + sc * o[4], c1.y + sc * o[5],
                                         c1.z + sc * o[6], c1.w + sc * o[7]);
    }
}

// ===========================================================================
extern "C" void kernel_launch(void* const* d_in, const int* in_sizes, int n_in,
                              void* d_out, int out_size) {
    const float* x    = (const float*)d_in[0];
    const float* W    = (const float*)d_in[1];
    const float* bias = (const float*)d_in[2];
    float* out = (float*)d_out;

    (void)in_sizes; (void)n_in; (void)out_size;

    cudaFuncSetAttribute(k_proj, cudaFuncAttributeMaxDynamicSharedMemorySize,
                         PROJ_SMEM);
    cudaFuncSetAttribute(k_sg, cudaFuncAttributeMaxDynamicSharedMemorySize,
                         SG_SMEM);

    k_xT<<<dim3(MTOT / 32, DD / 32, 1), 256>>>(x);
    k_proj<<<dim3(MTOT / 128, NQKV / 128, 1), 256, PROJ_SMEM>>>(W, bias);
    k_sg<<<256 + BB * TT * 4, 256, SG_SMEM>>>(out);
    k_prefix<<<512, 256>>>();
    k_inter<<<BB * 31 * 2, 256>>>(out);
}

// round 17
// speedup vs baseline: 1.1648x; 1.1648x over previous
#include <cuda_runtime.h>
#include <math.h>

// ---------------------------------------------------------------------------
// Retention, fully parallel chunked formulation (all FFMA2 / f32x2):
//   proj: qkv = x @ Wqkv + b   (reg-prefetch double buffered GEMM)
//   intra: out = (tril(alpha^{r-p}) * qk^T/16) @ V   ─┐ merged single launch
//   G_t[m,n] = sum_r alpha^(127-r) k[r,m] v[r,n]     ─┘
//   S_t = alpha^128 * S_{t-1} + G_{t-1}              (elementwise scan)
//   inter: out += alpha^(r+1)/16 * q @ S_t           (GEMM, exact 496 CTAs)
// ---------------------------------------------------------------------------

#define BB    8
#define LL    4096
#define DD    256
#define CC    128
#define TT    (LL / CC)
#define NQKV  768
#define MTOT  (BB * LL)
#define ALPHAF 0.99f

typedef unsigned long long u64t;

__device__ __forceinline__ u64t pk2(float a, float b) {
    u64t r; asm("mov.b64 %0, {%1,%2};" : "=l"(r) : "f"(a), "f"(b)); return r;
}
__device__ __forceinline__ void up2(u64t v, float& a, float& b) {
    asm("mov.b64 {%0,%1}, %2;" : "=f"(a), "=f"(b) : "l"(v));
}
__device__ __forceinline__ u64t ffma2(u64t a, u64t b, u64t c) {
    u64t d; asm("fma.rn.f32x2 %0, %1, %2, %3;" : "=l"(d) : "l"(a), "l"(b), "l"(c)); return d;
}

// ---- scratch (device globals; no runtime allocation) -----------------------
__device__ float g_q[MTOT * DD];
__device__ float g_k[MTOT * DD];
__device__ float g_v[MTOT * DD];
__device__ float g_G[BB * TT * DD * DD];   // G chunks, then S in-place

// 8x8 f32x2 microkernel step (proven): A broadcast via pk2, B as pairs.
#define MK_STEP(Abase, Bbase)                                                  \
    do {                                                                       \
        const float4 a0 = *(const float4*)(Abase);                             \
        const float4 a1 = *(const float4*)((Abase) + 4);                       \
        const u64t* wp = (const u64t*)(Bbase);                                 \
        const u64t w0 = wp[0], w1 = wp[1], w2 = wp[2], w3 = wp[3];             \
        float av[8] = {a0.x, a0.y, a0.z, a0.w, a1.x, a1.y, a1.z, a1.w};        \
        _Pragma("unroll")                                                      \
        for (int i = 0; i < 8; ++i) {                                          \
            u64t aa = pk2(av[i], av[i]);                                       \
            acc[i][0] = ffma2(aa, w0, acc[i][0]);                              \
            acc[i][1] = ffma2(aa, w1, acc[i][1]);                              \
            acc[i][2] = ffma2(aa, w2, acc[i][2]);                              \
            acc[i][3] = ffma2(aa, w3, acc[i][3]);                              \
        }                                                                      \
    } while (0)

// ===========================================================================
// Kernel 1: QKV projection (R14-proven reg-prefetch version).
// ===========================================================================
__global__ void __launch_bounds__(256, 2)
k_proj(const float* __restrict__ x,
       const float* __restrict__ W,
       const float* __restrict__ bias) {
    __shared__ __align__(16) float Xs[32 * 132];   // [kk][row]
    __shared__ __align__(16) float Wsm[32 * 132];  // [kk][col]

    const int tid = threadIdx.x;
    const int ty = tid >> 4, tx = tid & 15;
    const int m0 = blockIdx.x * 128;
    const int n0 = blockIdx.y * 128;

    float rx[16], rw[16];
    #pragma unroll
    for (int it = 0; it < 16; ++it) {
        int idx = tid + it * 256;
        rx[it] = x[(size_t)(m0 + (idx >> 5)) * DD + (idx & 31)];
        rw[it] = W[(size_t)(idx >> 7) * NQKV + n0 + (idx & 127)];
    }

    u64t acc[8][4] = {};

    for (int kt = 0; kt < 8; ++kt) {
        __syncthreads();
        #pragma unroll
        for (int it = 0; it < 16; ++it) {
            int idx = tid + it * 256;
            Xs[(idx & 31) * 132 + (idx >> 5)] = rx[it];
            Wsm[(idx >> 7) * 132 + (idx & 127)] = rw[it];
        }
        __syncthreads();

        if (kt < 7) {
            #pragma unroll
            for (int it = 0; it < 16; ++it) {
                int idx = tid + it * 256;
                rx[it] = x[(size_t)(m0 + (idx >> 5)) * DD + (kt + 1) * 32 + (idx & 31)];
                rw[it] = W[(size_t)((kt + 1) * 32 + (idx >> 7)) * NQKV + n0 + (idx & 127)];
            }
        }

        #pragma unroll
        for (int kk = 0; kk < 32; ++kk)
            MK_STEP(Xs + kk * 132 + ty * 8, Wsm + kk * 132 + tx * 8);
    }

    const int cg0 = n0 + tx * 8;
    const int which = cg0 >> 8;
    float* dst = (which == 0) ? g_q : (which == 1 ? g_k : g_v);
    const int off = cg0 & 255;
    float bv[8];
    #pragma unroll
    for (int u = 0; u < 8; ++u) bv[u] = bias[cg0 + u];

    #pragma unroll
    for (int i = 0; i < 8; ++i) {
        size_t mg = (size_t)(m0 + ty * 8 + i);
        float o[8];
        up2(acc[i][0], o[0], o[1]); up2(acc[i][1], o[2], o[3]);
        up2(acc[i][2], o[4], o[5]); up2(acc[i][3], o[6], o[7]);
        *(float4*)(dst + mg * DD + off) =
            make_float4(o[0] + bv[0], o[1] + bv[1], o[2] + bv[2], o[3] + bv[3]);
        *(float4*)(dst + mg * DD + off + 4) =
            make_float4(o[4] + bv[4], o[5] + bv[5], o[6] + bv[6], o[7] + bv[7]);
    }
}

// ===========================================================================
// Kernel 2 (merged): blockIdx < 256 -> fused intra (scores + A@V);
//                    blockIdx >= 256 -> chunk summaries G.
// Dyn smem = 101376 B; 2 CTAs/SM. Bodies identical to the proven R14 kernels.
// ===========================================================================
#define SG_SMEM ((128 * 132 + 2 * 32 * 132) * 4)

__device__ void scores2_body(int bx, float* __restrict__ out, float* smf) {
    float* As = smf;                  // [128][132]
    float* Qs = As + 128 * 132;       // [32][132]
    float* Ks = Qs + 32 * 132;        // [32][132]
    float* Vt = Qs;                   // [32][132] (aliases Qs in phase 2)
    __shared__ float tabB[128];

    const int tid = threadIdx.x;
    const int ty = tid >> 4, tx = tid & 15;
    const int bi = bx >> 5;
    const int t  = bx & 31;
    const size_t rowbase = (size_t)bi * LL + (size_t)t * CC;

    if (tid < 128) tabB[tid] = powf(ALPHAF, (float)tid) * 0.0625f;

    // ---- phase 1: scores, reg-prefetched ----
    {
        float rq[16], rk[16];
        #pragma unroll
        for (int it = 0; it < 16; ++it) {
            int idx = tid + it * 256;
            int kk = idx & 31, rr = idx >> 5;
            rq[it] = g_q[(rowbase + rr) * DD + kk];
            rk[it] = g_k[(rowbase + rr) * DD + kk];
        }

        u64t acc[8][4] = {};

        for (int kt = 0; kt < 8; ++kt) {
            __syncthreads();
            #pragma unroll
            for (int it = 0; it < 16; ++it) {
                int idx = tid + it * 256;
                int kk = idx & 31, rr = idx >> 5;
                Qs[kk * 132 + rr] = rq[it];
                Ks[kk * 132 + rr] = rk[it];
            }
            __syncthreads();

            if (kt < 7) {
                #pragma unroll
                for (int it = 0; it < 16; ++it) {
                    int idx = tid + it * 256;
                    int kk = idx & 31, rr = idx >> 5;
                    rq[it] = g_q[(rowbase + rr) * DD + (kt + 1) * 32 + kk];
                    rk[it] = g_k[(rowbase + rr) * DD + (kt + 1) * 32 + kk];
                }
            }

            #pragma unroll
            for (int kk = 0; kk < 32; ++kk)
                MK_STEP(Qs + kk * 132 + ty * 8, Ks + kk * 132 + tx * 8);
        }

        // decay + mask, park A in smem
        #pragma unroll
        for (int i = 0; i < 8; ++i) {
            const int rr = ty * 8 + i;
            float o[8];
            up2(acc[i][0], o[0], o[1]); up2(acc[i][1], o[2], o[3]);
            up2(acc[i][2], o[4], o[5]); up2(acc[i][3], o[6], o[7]);
            #pragma unroll
            for (int u = 0; u < 8; ++u) {
                int pp = tx * 8 + u;
                o[u] = (pp <= rr) ? o[u] * tabB[rr - pp] : 0.0f;
            }
            *(float4*)(As + rr * 132 + tx * 8)     = make_float4(o[0], o[1], o[2], o[3]);
            *(float4*)(As + rr * 132 + tx * 8 + 4) = make_float4(o[4], o[5], o[6], o[7]);
        }
    }

    // ---- phase 2: out = A @ V; V streamed as 8 tiles of 32 rows ----
    {
        float rv[16];
        #pragma unroll
        for (int it = 0; it < 16; ++it) {
            int idx = tid + it * 256;
            rv[it] = g_v[(rowbase + (idx >> 7)) * DD + (idx & 127)];
        }

        for (int nh = 0; nh < 2; ++nh) {
            u64t acc[8][4] = {};
            for (int jt = 0; jt < 4; ++jt) {
                const int s = nh * 4 + jt;
                __syncthreads();
                #pragma unroll
                for (int it = 0; it < 16; ++it) {
                    int idx = tid + it * 256;
                    Vt[(idx >> 7) * 132 + (idx & 127)] = rv[it];
                }
                __syncthreads();

                if (s < 7) {
                    const int nh2 = (s + 1) >> 2, jt2 = (s + 1) & 3;
                    #pragma unroll
                    for (int it = 0; it < 16; ++it) {
                        int idx = tid + it * 256;
                        rv[it] = g_v[(rowbase + jt2 * 32 + (idx >> 7)) * DD
                                     + nh2 * 128 + (idx & 127)];
                    }
                }

                #pragma unroll
                for (int j4 = 0; j4 < 8; ++j4) {
                    float av[8][4];
                    #pragma unroll
                    for (int i = 0; i < 8; ++i)
                        *(float4*)av[i] =
                            *(const float4*)(As + (ty * 8 + i) * 132 + jt * 32 + j4 * 4);
                    #pragma unroll
                    for (int jj = 0; jj < 4; ++jj) {
                        const u64t* vp = (const u64t*)(Vt + (j4 * 4 + jj) * 132 + tx * 8);
                        const u64t w0 = vp[0], w1 = vp[1], w2 = vp[2], w3 = vp[3];
                        #pragma unroll
                        for (int i = 0; i < 8; ++i) {
                            u64t aa = pk2(av[i][jj], av[i][jj]);
                            acc[i][0] = ffma2(aa, w0, acc[i][0]);
                            acc[i][1] = ffma2(aa, w1, acc[i][1]);
                            acc[i][2] = ffma2(aa, w2, acc[i][2]);
                            acc[i][3] = ffma2(aa, w3, acc[i][3]);
                        }
                    }
                }
            }

            #pragma unroll
            for (int i = 0; i < 8; ++i) {
                float o[8];
                up2(acc[i][0], o[0], o[1]); up2(acc[i][1], o[2], o[3]);
                up2(acc[i][2], o[4], o[5]); up2(acc[i][3], o[6], o[7]);
                float* op = out + (rowbase + ty * 8 + i) * DD + nh * 128 + tx * 8;
                *(float4*)op       = make_float4(o[0], o[1], o[2], o[3]);
                *(float4*)(op + 4) = make_float4(o[4], o[5], o[6], o[7]);
            }
        }
    }
}

__device__ void G_body(int bx, float* smf) {
    float* Kd = smf;                  // [32][132]
    float* Vs = Kd + 32 * 132;        // [32][132]
    __shared__ float tabA[128];

    const int tid = threadIdx.x;
    const int ty = tid >> 4, tx = tid & 15;
    const int bt = bx >> 2;
    const int quad = bx & 3;
    const int mi = quad >> 1, ni = quad & 1;
    const int b = bt >> 5, t = bt & 31;
    const size_t rowbase = (size_t)b * LL + (size_t)t * CC;

    if (tid < 128) tabA[tid] = powf(ALPHAF, (float)(127 - tid));
    __syncthreads();

    float4 rk4[4], rv4[4];
    #pragma unroll
    for (int it = 0; it < 4; ++it) {
        int i4 = tid + it * 256;
        int m4 = i4 & 31, rr = i4 >> 5;
        rk4[it] = *(const float4*)(g_k + (rowbase + rr) * DD + mi * 128 + m4 * 4);
        rv4[it] = *(const float4*)(g_v + (rowbase + rr) * DD + ni * 128 + m4 * 4);
    }

    u64t acc[8][4] = {};

    for (int rt = 0; rt < 4; ++rt) {
        __syncthreads();
        #pragma unroll
        for (int it = 0; it < 4; ++it) {
            int i4 = tid + it * 256;
            int m4 = i4 & 31, rr = i4 >> 5;
            float sc = tabA[rt * 32 + rr];
            *(float4*)(Kd + rr * 132 + m4 * 4) =
                make_float4(rk4[it].x * sc, rk4[it].y * sc, rk4[it].z * sc, rk4[it].w * sc);
            *(float4*)(Vs + rr * 132 + m4 * 4) = rv4[it];
        }
        __syncthreads();

        if (rt < 3) {
            #pragma unroll
            for (int it = 0; it < 4; ++it) {
                int i4 = tid + it * 256;
                int m4 = i4 & 31, rr = i4 >> 5;
                rk4[it] = *(const float4*)(g_k + (rowbase + (rt + 1) * 32 + rr) * DD
                                           + mi * 128 + m4 * 4);
                rv4[it] = *(const float4*)(g_v + (rowbase + (rt + 1) * 32 + rr) * DD
                                           + ni * 128 + m4 * 4);
            }
        }

        #pragma unroll
        for (int kk = 0; kk < 32; ++kk)
            MK_STEP(Kd + kk * 132 + ty * 8, Vs + kk * 132 + tx * 8);
    }

    float* Gd = g_G + ((size_t)bt << 16);
    #pragma unroll
    for (int i = 0; i < 8; ++i) {
        float o[8];
        up2(acc[i][0], o[0], o[1]); up2(acc[i][1], o[2], o[3]);
        up2(acc[i][2], o[4], o[5]); up2(acc[i][3], o[6], o[7]);
        float* gp = Gd + (size_t)(mi * 128 + ty * 8 + i) * DD + ni * 128 + tx * 8;
        *(float4*)gp       = make_float4(o[0], o[1], o[2], o[3]);
        *(float4*)(gp + 4) = make_float4(o[4], o[5], o[6], o[7]);
    }
}

__global__ void __launch_bounds__(256, 2) k_sg(float* __restrict__ out) {
    extern __shared__ __align__(16) float smf[];
    if (blockIdx.x < 256) scores2_body(blockIdx.x, out, smf);   // long CTAs first
    else                  G_body(blockIdx.x - 256, smf);
}

// ===========================================================================
// Kernel 3: elementwise prefix scan, 2-deep prefetch (MLP 3).
// ===========================================================================
__global__ void k_prefix() {
    const int id = blockIdx.x * 256 + threadIdx.x;
    const int b = id >> 14;
    const int e4 = id & 16383;
    float4* p = (float4*)g_G + ((size_t)b * 32) * 16384 + e4;
    const float a128 = powf(ALPHAF, 128.0f);
    float4 s = make_float4(0.f, 0.f, 0.f, 0.f);
    float4 g0 = p[0];
    float4 g1 = p[16384];
    #pragma unroll
    for (int t = 0; t < TT; ++t) {
        float4 gn = make_float4(0.f, 0.f, 0.f, 0.f);
        if (t + 2 < TT) gn = p[(size_t)(t + 2) * 16384];
        p[(size_t)t * 16384] = s;
        s.x = fmaf(a128, s.x, g0.x); s.y = fmaf(a128, s.y, g0.y);
        s.z = fmaf(a128, s.z, g0.z); s.w = fmaf(a128, s.w, g0.w);
        g0 = g1; g1 = gn;
    }
}

// ===========================================================================
// Kernel 4: inter-chunk: out += alpha^(r+1)/16 * q @ S_t   (496 CTAs exact)
// ===========================================================================
__global__ void __launch_bounds__(256, 2) k_inter(float* __restrict__ out) {
    const int b  = blockIdx.x / 62;
    const int r  = blockIdx.x % 62;
    const int t  = (r >> 1) + 1;         // 1..31
    const int nh = r & 1;
    const int bt = b * 32 + t;

    __shared__ __align__(16) float Qs[32 * 132];
    __shared__ __align__(16) float Ss[32 * 132];

    const int tid = threadIdx.x;
    const int ty = tid >> 4, tx = tid & 15;
    const size_t rowbase = (size_t)b * LL + (size_t)t * CC;
    const float* Sbase = g_G + ((size_t)bt << 16);

    float rq[16];
    float4 rs4[4];
    #pragma unroll
    for (int it = 0; it < 16; ++it) {
        int idx = tid + it * 256;
        rq[it] = g_q[(rowbase + (idx >> 5)) * DD + (idx & 31)];
    }
    #pragma unroll
    for (int it = 0; it < 4; ++it) {
        int i4 = tid + it * 256;
        rs4[it] = *(const float4*)(Sbase + (size_t)(i4 >> 5) * DD + nh * 128 + (i4 & 31) * 4);
    }

    u64t acc[8][4] = {};

    for (int kt = 0; kt < 8; ++kt) {
        __syncthreads();
        #pragma unroll
        for (int it = 0; it < 16; ++it) {
            int idx = tid + it * 256;
            Qs[(idx & 31) * 132 + (idx >> 5)] = rq[it];
        }
        #pragma unroll
        for (int it = 0; it < 4; ++it) {
            int i4 = tid + it * 256;
            *(float4*)(Ss + (i4 >> 5) * 132 + (i4 & 31) * 4) = rs4[it];
        }
        __syncthreads();

        if (kt < 7) {
            #pragma unroll
            for (int it = 0; it < 16; ++it) {
                int idx = tid + it * 256;
                rq[it] = g_q[(rowbase + (idx >> 5)) * DD + (kt + 1) * 32 + (idx & 31)];
            }
            #pragma unroll
            for (int it = 0; it < 4; ++it) {
                int i4 = tid + it * 256;
                rs4[it] = *(const float4*)(Sbase + (size_t)((kt + 1) * 32 + (i4 >> 5)) * DD
                                           + nh * 128 + (i4 & 31) * 4);
            }
        }

        #pragma unroll
        for (int kk = 0; kk < 32; ++kk)
            MK_STEP(Qs + kk * 132 + ty * 8, Ss + kk * 132 + tx * 8);
    }

    #pragma unroll
    for (int i = 0; i < 8; ++i) {
        const int rr = ty * 8 + i;
        const float sc = powf(ALPHAF, (float)(rr + 1)) * 0.0625f;
        float o[8];
        up2(acc[i][0], o[0], o[1]); up2(acc[i][1], o[2], o[3]);
        up2(acc[i][2], o[4], o[5]); up2(acc[i][3], o[6], o[7]);
        float* op = out + (rowbase + rr) * DD + nh * 128 + tx * 8;
        float4 c0 = *(const float4*)op;
        float4 c1 = *(const float4*)(op + 4);
        *(float4*)op = make_float4(c0.x + sc * o[0], c0.y + sc * o[1],
                                   c0.z + sc * o[2], c0.w + sc * o[3]);
        *(float4*)(op + 4) = make_float4(c1.x + sc * o[4], c1.y + sc * o[5],
                                         c1.z + sc * o[6], c1.w + sc * o[7]);
    }
}

// ===========================================================================
extern "C" void kernel_launch(void* const* d_in, const int* in_sizes, int n_in,
                              void* d_out, int out_size) {
    const float* x    = (const float*)d_in[0];
    const float* W    = (const float*)d_in[1];
    const float* bias = (const float*)d_in[2];
    float* out = (float*)d_out;

    (void)in_sizes; (void)n_in; (void)out_size;

    cudaFuncSetAttribute(k_sg, cudaFuncAttributeMaxDynamicSharedMemorySize,
                         SG_SMEM);

    k_proj<<<dim3(MTOT / 128, NQKV / 128, 1), 256>>>(x, W, bias);
    k_sg<<<256 + BB * TT * 4, 256, SG_SMEM>>>(out);
    k_prefix<<<512, 256>>>();
    k_inter<<<BB * 31 * 2, 256>>>(out);
}